// round 8
// baseline (speedup 1.0000x reference)
#include <cuda_runtime.h>
#include <cuda_bf16.h>
#include <cstdint>
#include <math.h>

#define T_STEPS 2048
#define B_ROWS  64
#define TNO     501
#define NBASIS  30
#define NEAR    12      // delays 1..12 live in decision-thread registers
#define ACC_N   512     // far-delay accumulator ring (power of 2 > TNO)
#define ACC_M   511
#define NTH     128
#define DBATCH  8       // decision batch (1 poll pair per 8 steps)

#define PROBE_CYCLES 6000000LL   // clock-rate probe: dur -= 1047us -> f = 6e6/dt

// ---------------------------------------------------------------------------
// Threefry-2x32, 20 rounds — bit-exact port of jax/_src/prng.py threefry2x32
// ---------------------------------------------------------------------------
__device__ __forceinline__ void tf2x32(uint32_t k0, uint32_t k1,
                                       uint32_t x0, uint32_t x1,
                                       uint32_t &o0, uint32_t &o1) {
    uint32_t k2 = k0 ^ k1 ^ 0x1BD11BDAu;
#define TFR(r) { x0 += x1; x1 = __funnelshift_l(x1, x1, (r)); x1 ^= x0; }
    x0 += k0; x1 += k1;
    TFR(13) TFR(15) TFR(26) TFR(6)
    x0 += k1; x1 += k2 + 1u;
    TFR(17) TFR(29) TFR(16) TFR(24)
    x0 += k2; x1 += k0 + 2u;
    TFR(13) TFR(15) TFR(26) TFR(6)
    x0 += k0; x1 += k1 + 3u;
    TFR(17) TFR(29) TFR(16) TFR(24)
    x0 += k1; x1 += k2 + 4u;
    TFR(13) TFR(15) TFR(26) TFR(6)
    x0 += k2; x1 += k0 + 5u;
#undef TFR
    o0 = x0; o1 = x1;
}

// XLA EmitTanh (Eigen rational, clamp [-9,9], |x|<4e-4 -> x), UNcontracted.
// This exact form gave rel_err 8e-8 (zero Bernoulli flips). DO NOT TOUCH.
__device__ __forceinline__ float tanh_xla(float x) {
    float ax = fabsf(x);
    float xc = fminf(fmaxf(x, -9.0f), 9.0f);
    float x2 = __fmul_rn(xc, xc);
    float num = -2.76076847742355e-16f;
    num = __fadd_rn(__fmul_rn(x2, num),  2.00018790482477e-13f);
    num = __fadd_rn(__fmul_rn(x2, num), -8.60467152213735e-11f);
    num = __fadd_rn(__fmul_rn(x2, num),  5.12229709037114e-08f);
    num = __fadd_rn(__fmul_rn(x2, num),  1.48572235717979e-05f);
    num = __fadd_rn(__fmul_rn(x2, num),  6.37261928875436e-04f);
    num = __fadd_rn(__fmul_rn(x2, num),  4.89352455891786e-03f);
    num = __fmul_rn(xc, num);
    float den = 1.19825839466702e-06f;
    den = __fadd_rn(__fmul_rn(x2, den),  1.18534705686654e-04f);
    den = __fadd_rn(__fmul_rn(x2, den),  2.26843463243900e-03f);
    den = __fadd_rn(__fmul_rn(x2, den),  4.89352518554385e-03f);
    float r = __fdiv_rn(num, den);
    return (ax < 0.0004f) ? x : r;
}
// P = 0.5*tanh(0.5*x)+0.5  (bit-identical to the passing kernel's sequence)
__device__ __forceinline__ float sigP(float x) {
    return __fadd_rn(__fmul_rn(0.5f, tanh_xla(__fmul_rn(0.5f, x))), 0.5f);
}

__device__ __forceinline__ void st_rel(int *p, int v) {
    uint32_t a = (uint32_t)__cvta_generic_to_shared(p);
    asm volatile("st.release.cta.shared.b32 [%0], %1;" :: "r"(a), "r"(v) : "memory");
}
__device__ __forceinline__ int ldv(volatile int *p) { return *p; }

// ---------------------------------------------------------------------------
// Clock probe: spins for exactly PROBE_CYCLES SM cycles.  Launched as a
// second graph node after the real kernel; the added wall time reveals the
// SM frequency in the exact low-load regime the real kernel runs in:
//     f_SM = PROBE_CYCLES / (dur_us - 1047us)
// ---------------------------------------------------------------------------
__global__ void clock_probe_kernel() {
    if (threadIdx.x == 0) {
        long long start = clock64();
        while (clock64() - start < PROBE_CYCLES) { }
    }
}

// ---------------------------------------------------------------------------
// One block per row b.  (R7 kernel, verbatim — known 1046.7us / 8.09e-8.)
//   tid 0      : key-split chain (free-run, zero polls, release every 2)
//   tids 32-35 : uniform producers, 4 steps per poll
//   tid 64     : decision, 8 straight-line speculative steps per poll pair
//   tids 96-127: scatter, branch-free fmaf, 2 steps per poll
// Warps 2+3 do the heavy init (f64 basis, MLP) while warps 0,1 free-run.
// ---------------------------------------------------------------------------
__global__ __launch_bounds__(NTH)
void apnn_kernel(const float *__restrict__ V,  const float *__restrict__ D,
                 const float *__restrict__ w1, const float *__restrict__ b1,
                 const float *__restrict__ w2, const float *__restrict__ b2,
                 const float *__restrict__ Wref, float *__restrict__ out) {
    __shared__ float    nnrow[T_STEPS + DBATCH]; // MLP output (+pad for lookahead)
    __shared__ uint32_t subring[T_STEPS][2];     // per-step subkeys
    __shared__ float    uring[T_STEPS];          // per-step uniforms
    __shared__ float    spikering[T_STEPS];      // spikes
    __shared__ float    acc[ACC_N];              // pending far refract
    __shared__ float    wdel[TNO];               // weight for delay j+1
    __shared__ int      chain_seq, u_seq, dec_seq, scatter_seq;

    const int tid = threadIdx.x;
    const int b   = blockIdx.x;

    if (tid == 0) { chain_seq = 0; u_seq = 0; dec_seq = 0; scatter_seq = 0; }
    __syncthreads();

    if (tid == 0) {
        // ---- chain: free-running serial split chain, 2 steps per release.
        // new_key = tf(key,(0,0)); sub = tf(key,(0,1))
        uint32_t k0 = 0u, k1 = 42u;              // jax.random.key(42) -> (0,42)
        for (int base = 0; base < T_STEPS; base += 2) {
            uint32_t nk0, nk1, s0, s1;
            tf2x32(k0, k1, 0u, 0u, nk0, nk1);
            tf2x32(k0, k1, 0u, 1u, s0, s1);
            subring[base][0] = s0;  subring[base][1] = s1;
            k0 = nk0; k1 = nk1;
            tf2x32(k0, k1, 0u, 0u, nk0, nk1);
            tf2x32(k0, k1, 0u, 1u, s0, s1);
            subring[base + 1][0] = s0;  subring[base + 1][1] = s1;
            k0 = nk0; k1 = nk1;
            st_rel(&chain_seq, base + 2);
        }
    } else if (tid >= 32 && tid < 36) {
        // ---- uniform: 4 lanes, 4 steps per poll. bits = y0^y1 of tf(sub,(0,b))
        const int lane = tid - 32;
        int cs = 0;
        for (int base = 0; base < T_STEPS; base += 4) {
            if (cs < base + 4) { do { cs = ldv(&chain_seq); } while (cs < base + 4); }
            int t = base + lane;
            uint32_t s0 = subring[t][0];
            uint32_t s1 = subring[t][1];
            uint32_t y0, y1;
            tf2x32(s0, s1, 0u, (uint32_t)b, y0, y1);
            uint32_t bits = y0 ^ y1;
            uring[t] = __uint_as_float((bits >> 9) | 0x3F800000u) - 1.0f;
            __syncwarp(0xFu);
            if (lane == 0) st_rel(&u_seq, base + 4);
        }
    } else if (tid >= 64) {
        // ---- init on warps 2+3 (64 threads), overlapped with chain/uniform
        const int itid = tid - 64;
        for (int i = itid; i < ACC_N; i += 64) acc[i] = 0.0f;
        if (itid < DBATCH) nnrow[T_STEPS + itid] = 0.0f;   // lookahead pad
        // refractory delay weights: wdel[j] = sum_i f32(basis_f64[i,j])*Wref[i]
        for (int j = itid; j < TNO; j += 64) {
            double raw = 7.5 * log(((double)j + 1.0) + 1e-7);
            double cr = cos(raw), sr = sin(raw);
            float s = 0.0f;
            #pragma unroll 1
            for (int i = 0; i < NBASIS; i++) {
                double phi = 1.5707963267948966 * (double)i;
                float bas = 0.0f;
                if (!(raw < phi - 3.141592653589793 || raw > phi + 3.141592653589793)) {
                    double cv;
                    switch (i & 3) {
                        case 0:  cv =  cr; break;
                        case 1:  cv =  sr; break;
                        case 2:  cv = -cr; break;
                        default: cv = -sr; break;
                    }
                    bas = (float)(0.5 * cv + 0.5);
                }
                s = __fmaf_rn(bas, Wref[i], s);
            }
            wdel[j] = s;
        }
        // pointwise MLP
        {
            float a0 = w1[0], a1 = w1[1], a2 = w1[2], a3 = w1[3], a4 = w1[4];
            float a5 = w1[5], a6 = w1[6], a7 = w1[7], a8 = w1[8], a9 = w1[9];
            float c0 = b1[0], c1 = b1[1], c2 = b1[2], c3 = b1[3], c4 = b1[4];
            float v0 = w2[0], v1 = w2[1], v2 = w2[2], v3 = w2[3], v4 = w2[4];
            float bb = b2[0];
            const float *Vr = V + (size_t)b * T_STEPS;
            const float *Dr = D + (size_t)b * T_STEPS;
            for (int t = itid; t < T_STEPS; t += 64) {
                float vv = Vr[t], dd = Dr[t];
                float h0 = tanh_xla(__fadd_rn(__fadd_rn(__fmul_rn(a0, vv), __fmul_rn(a1, dd)), c0));
                float h1 = tanh_xla(__fadd_rn(__fadd_rn(__fmul_rn(a2, vv), __fmul_rn(a3, dd)), c1));
                float h2 = tanh_xla(__fadd_rn(__fadd_rn(__fmul_rn(a4, vv), __fmul_rn(a5, dd)), c2));
                float h3 = tanh_xla(__fadd_rn(__fadd_rn(__fmul_rn(a6, vv), __fmul_rn(a7, dd)), c3));
                float h4 = tanh_xla(__fadd_rn(__fadd_rn(__fmul_rn(a8, vv), __fmul_rn(a9, dd)), c4));
                float s = __fmul_rn(v0, h0);
                s = __fadd_rn(s, __fmul_rn(v1, h1));
                s = __fadd_rn(s, __fmul_rn(v2, h2));
                s = __fadd_rn(s, __fmul_rn(v3, h3));
                s = __fadd_rn(s, __fmul_rn(v4, h4));
                nnrow[t] = __fadd_rn(s, bb);
            }
        }
        asm volatile("bar.sync 1, 64;" ::: "memory");   // warps 2+3 only

        if (tid == 64) {
            // ---- decision: 8 straight-line speculative steps per poll pair.
            // Virtual f1: candidates for step t+1 branch on spike(t):
            //   cand0 uses f2, cand1 uses fadd(wd0,f2)  (== fmaf(wd0,{0,1},f2))
            float f2 = 0.f, f3 = 0.f, f4 = 0.f, f5 = 0.f, f6 = 0.f, f7 = 0.f,
                  f8 = 0.f, f9 = 0.f, f10 = 0.f, f11 = 0.f, f12 = 0.f;
            const float wd0 = wdel[0],  wd1 = wdel[1],  wd2 = wdel[2],  wd3 = wdel[3];
            const float wd4 = wdel[4],  wd5 = wdel[5],  wd6 = wdel[6],  wd7 = wdel[7];
            const float wd8 = wdel[8],  wd9 = wdel[9],  wd10 = wdel[10], wd11 = wdel[11];
            float *Sout = out + (size_t)b * T_STEPS;
            float *Pout = out + (size_t)B_ROWS * T_STEPS + (size_t)b * T_STEPS;
            int us = 0, ss = 0;
            // prologue: candidates for t = 0 (all-zero history) — R5 bit sequence
            float far0 = acc[0]; acc[0] = 0.0f;
            float nn0  = nnrow[0];
            float Pc0 = sigP(__fadd_rn(nn0, __fadd_rn(far0, f2)));
            float Pc1 = sigP(__fadd_rn(nn0, __fadd_rn(far0, __fadd_rn(wd0, f2))));
            bool  sp_prev = false;
            for (int B = 0; B < T_STEPS; B += DBATCH) {
                // one poll pair per batch
                if (us < B + DBATCH) { do { us = ldv(&u_seq); } while (us < B + DBATCH); }
                int need = B - 4;     // covers far-writes for slots B+1..B+8
                if (ss < need) { do { ss = ldv(&scatter_seq); } while (ss < need); }
                // preload batch operands (LDS latencies overlap)
                float uu[DBATCH], nn[DBATCH], fr[DBATCH];
                #pragma unroll
                for (int i = 0; i < DBATCH; i++) uu[i] = uring[B + i];
                #pragma unroll
                for (int i = 0; i < DBATCH; i++) nn[i] = nnrow[B + 1 + i];
                #pragma unroll
                for (int i = 0; i < DBATCH; i++) {
                    int sl = (B + 1 + i) & ACC_M;
                    fr[i] = acc[sl];
                    acc[sl] = 0.0f;               // recycle for step sl+512
                }
                // 8 branch-free steps
                #pragma unroll
                for (int i = 0; i < DBATCH; i++) {
                    int t = B + i;
                    // A: speculative candidates for step t+1 (R5 bit sequence)
                    float x0 = __fadd_rn(nn[i], __fadd_rn(fr[i], f2));
                    float x1 = __fadd_rn(nn[i], __fadd_rn(fr[i], __fadd_rn(wd0, f2)));
                    float Pn0 = sigP(x0);
                    float Pn1 = sigP(x1);
                    // B: resolve step t with previous candidates
                    float P   = sp_prev ? Pc1 : Pc0;
                    bool  sp  = (uu[i] < P);
                    float spf = sp ? 1.0f : 0.0f;
                    Sout[t] = spf;
                    Pout[t] = P;
                    spikering[t] = spf;
                    // C: shift near-delay registers with spike(t)
                    f2  = __fmaf_rn(wd1,  spf, f3);
                    f3  = __fmaf_rn(wd2,  spf, f4);
                    f4  = __fmaf_rn(wd3,  spf, f5);
                    f5  = __fmaf_rn(wd4,  spf, f6);
                    f6  = __fmaf_rn(wd5,  spf, f7);
                    f7  = __fmaf_rn(wd6,  spf, f8);
                    f8  = __fmaf_rn(wd7,  spf, f9);
                    f9  = __fmaf_rn(wd8,  spf, f10);
                    f10 = __fmaf_rn(wd9,  spf, f11);
                    f11 = __fmaf_rn(wd10, spf, f12);
                    f12 = __fmul_rn(wd11, spf);
                    Pc0 = Pn0; Pc1 = Pn1; sp_prev = sp;
                    if (i & 1) st_rel(&dec_seq, t + 1);   // releases B+2,B+4,B+6,B+8
                }
            }
        } else if (tid >= 96) {
            // ---- scatter: far delays d = 13..501, branch-free fmaf, 2 steps/poll
            const int lane = tid - 96;
            int ds = 0;
            for (int base = 0; base < T_STEPS; base += 2) {
                if (ds < base + 2) { do { ds = ldv(&dec_seq); } while (ds < base + 2); }
                #pragma unroll
                for (int q = 0; q < 2; q++) {
                    int t = base + q;
                    float spf = spikering[t];
                    // fmaf(w, spf, a): spf=1 -> w+a (== fadd), spf=0 -> a. Bit-exact.
                    #pragma unroll 4
                    for (int d = NEAR + 1 + lane; d <= TNO; d += 32) {
                        int sl = (t + d) & ACC_M;   // consecutive lanes: conflict-free
                        acc[sl] = __fmaf_rn(wdel[d - 1], spf, acc[sl]);
                    }
                }
                __syncwarp();
                if (lane == 0) st_rel(&scatter_seq, base + 2);
            }
        }
    }
}

extern "C" void kernel_launch(void* const* d_in, const int* in_sizes, int n_in,
                              void* d_out, int out_size) {
    const float *V    = (const float*)d_in[0];
    const float *D    = (const float*)d_in[1];
    const float *w1   = (const float*)d_in[2];
    const float *b1   = (const float*)d_in[3];
    const float *w2   = (const float*)d_in[4];
    const float *b2   = (const float*)d_in[5];
    const float *Wref = (const float*)d_in[6];
    float *out = (float*)d_out;
    apnn_kernel<<<B_ROWS, NTH>>>(V, D, w1, b1, w2, b2, Wref, out);
    // Clock-rate probe (second graph node): adds exactly 6e6 SM cycles of
    // wall time.  f_SM = 6e6 / (dur_us - 1046.7us).  Removed next round.
    clock_probe_kernel<<<1, 32>>>();
}

// round 9
// speedup vs baseline: 1.2973x; 1.2973x over previous
#include <cuda_runtime.h>
#include <cuda_bf16.h>
#include <cstdint>
#include <math.h>

#define T_STEPS 2048
#define B_ROWS  64
#define TNO     501
#define NBASIS  30
#define NEAR    12      // delays 1..12 live in decision-thread registers
#define ACC_N   512     // far-delay accumulator ring (power of 2 > TNO)
#define ACC_M   511
#define NTH     128
#define DBATCH  8       // decision batch (1 poll pair per 8 steps)

// ablation sinks (static __device__ globals — allowed scratch)
__device__ float    g_sink_chain[B_ROWS];
__device__ float    g_abl_S[B_ROWS * T_STEPS];
__device__ float    g_abl_P[B_ROWS * T_STEPS];

// ---------------------------------------------------------------------------
// Threefry-2x32, 20 rounds — bit-exact port of jax/_src/prng.py threefry2x32
// ---------------------------------------------------------------------------
__device__ __forceinline__ void tf2x32(uint32_t k0, uint32_t k1,
                                       uint32_t x0, uint32_t x1,
                                       uint32_t &o0, uint32_t &o1) {
    uint32_t k2 = k0 ^ k1 ^ 0x1BD11BDAu;
#define TFR(r) { x0 += x1; x1 = __funnelshift_l(x1, x1, (r)); x1 ^= x0; }
    x0 += k0; x1 += k1;
    TFR(13) TFR(15) TFR(26) TFR(6)
    x0 += k1; x1 += k2 + 1u;
    TFR(17) TFR(29) TFR(16) TFR(24)
    x0 += k2; x1 += k0 + 2u;
    TFR(13) TFR(15) TFR(26) TFR(6)
    x0 += k0; x1 += k1 + 3u;
    TFR(17) TFR(29) TFR(16) TFR(24)
    x0 += k1; x1 += k2 + 4u;
    TFR(13) TFR(15) TFR(26) TFR(6)
    x0 += k2; x1 += k0 + 5u;
#undef TFR
    o0 = x0; o1 = x1;
}

// XLA EmitTanh (Eigen rational, clamp [-9,9], |x|<4e-4 -> x), UNcontracted.
// This exact form gave rel_err 8e-8 (zero Bernoulli flips). DO NOT TOUCH.
__device__ __forceinline__ float tanh_xla(float x) {
    float ax = fabsf(x);
    float xc = fminf(fmaxf(x, -9.0f), 9.0f);
    float x2 = __fmul_rn(xc, xc);
    float num = -2.76076847742355e-16f;
    num = __fadd_rn(__fmul_rn(x2, num),  2.00018790482477e-13f);
    num = __fadd_rn(__fmul_rn(x2, num), -8.60467152213735e-11f);
    num = __fadd_rn(__fmul_rn(x2, num),  5.12229709037114e-08f);
    num = __fadd_rn(__fmul_rn(x2, num),  1.48572235717979e-05f);
    num = __fadd_rn(__fmul_rn(x2, num),  6.37261928875436e-04f);
    num = __fadd_rn(__fmul_rn(x2, num),  4.89352455891786e-03f);
    num = __fmul_rn(xc, num);
    float den = 1.19825839466702e-06f;
    den = __fadd_rn(__fmul_rn(x2, den),  1.18534705686654e-04f);
    den = __fadd_rn(__fmul_rn(x2, den),  2.26843463243900e-03f);
    den = __fadd_rn(__fmul_rn(x2, den),  4.89352518554385e-03f);
    float r = __fdiv_rn(num, den);
    return (ax < 0.0004f) ? x : r;
}
// P = 0.5*tanh(0.5*x)+0.5  (bit-identical to the passing kernel's sequence)
__device__ __forceinline__ float sigP(float x) {
    return __fadd_rn(__fmul_rn(0.5f, tanh_xla(__fmul_rn(0.5f, x))), 0.5f);
}

__device__ __forceinline__ void st_rel(int *p, int v) {
    uint32_t a = (uint32_t)__cvta_generic_to_shared(p);
    asm volatile("st.release.cta.shared.b32 [%0], %1;" :: "r"(a), "r"(v) : "memory");
}
__device__ __forceinline__ int ldv(volatile int *p) { return *p; }

// ===========================================================================
// ABLATION KERNEL 1: the chain warp in isolation, 4 passes over 2048 steps.
// Same residency (64 blocks), same code shape as the real chain stage.
// Contribution to graph time ~= 4 * C  (C = standalone chain stage time).
// ===========================================================================
__global__ __launch_bounds__(32)
void chain4_kernel() {
    __shared__ uint32_t subring[T_STEPS][2];
    __shared__ int      chain_seq;
    if (threadIdx.x == 0) {
        chain_seq = 0;
        uint32_t acc_sink = 0;
        for (int rep = 0; rep < 4; rep++) {
            uint32_t k0 = 0u, k1 = 42u;
            for (int base = 0; base < T_STEPS; base += 2) {
                uint32_t nk0, nk1, s0, s1;
                tf2x32(k0, k1, 0u, 0u, nk0, nk1);
                tf2x32(k0, k1, 0u, 1u, s0, s1);
                subring[base][0] = s0;  subring[base][1] = s1;
                k0 = nk0; k1 = nk1;
                tf2x32(k0, k1, 0u, 0u, nk0, nk1);
                tf2x32(k0, k1, 0u, 1u, s0, s1);
                subring[base + 1][0] = s0;  subring[base + 1][1] = s1;
                k0 = nk0; k1 = nk1;
                st_rel(&chain_seq, base + 2);
            }
            acc_sink ^= k0 ^ subring[2047][1];
        }
        g_sink_chain[blockIdx.x] = (float)(acc_sink & 0xFFFF);
    }
}

// ===========================================================================
// ABLATION KERNEL 2: decision + scatter coupled pair in isolation.
// Uniform/chain stages replaced by pre-filled synthetic data (u_seq
// pre-satisfied), so the measured time D is the dec<->scatter coupling rate.
// Code for the two roles is VERBATIM from the real kernel.
// ===========================================================================
__global__ __launch_bounds__(NTH)
void dec_scatter_kernel() {
    __shared__ float    nnrow[T_STEPS + DBATCH];
    __shared__ float    uring[T_STEPS];
    __shared__ float    spikering[T_STEPS];
    __shared__ float    acc[ACC_N];
    __shared__ float    wdel[TNO];
    __shared__ int      u_seq, dec_seq, scatter_seq;

    const int tid = threadIdx.x;
    const int b   = blockIdx.x;

    // synthetic, cheap, deterministic init
    if (tid == 0) { u_seq = T_STEPS; dec_seq = 0; scatter_seq = 0; }
    for (int i = tid; i < ACC_N; i += NTH) acc[i] = 0.0f;
    for (int j = tid; j < TNO; j += NTH) wdel[j] = __sinf((float)j * 0.37f) * 0.02f;
    for (int t = tid; t < T_STEPS + DBATCH; t += NTH)
        nnrow[t] = __sinf((float)t * 0.013f) * 2.0f - 1.0f;
    for (int t = tid; t < T_STEPS; t += NTH)
        uring[t] = 0.5f + 0.45f * __sinf((float)t * 1.7f);
    __syncthreads();

    if (tid == 64) {
        // decision — verbatim structure from the real kernel
        float f2 = 0.f, f3 = 0.f, f4 = 0.f, f5 = 0.f, f6 = 0.f, f7 = 0.f,
              f8 = 0.f, f9 = 0.f, f10 = 0.f, f11 = 0.f, f12 = 0.f;
        const float wd0 = wdel[0],  wd1 = wdel[1],  wd2 = wdel[2],  wd3 = wdel[3];
        const float wd4 = wdel[4],  wd5 = wdel[5],  wd6 = wdel[6],  wd7 = wdel[7];
        const float wd8 = wdel[8],  wd9 = wdel[9],  wd10 = wdel[10], wd11 = wdel[11];
        float *Sout = g_abl_S + (size_t)b * T_STEPS;
        float *Pout = g_abl_P + (size_t)b * T_STEPS;
        int us = 0, ss = 0;
        float far0 = acc[0]; acc[0] = 0.0f;
        float nn0  = nnrow[0];
        float Pc0 = sigP(__fadd_rn(nn0, __fadd_rn(far0, f2)));
        float Pc1 = sigP(__fadd_rn(nn0, __fadd_rn(far0, __fadd_rn(wd0, f2))));
        bool  sp_prev = false;
        for (int B = 0; B < T_STEPS; B += DBATCH) {
            if (us < B + DBATCH) { do { us = ldv(&u_seq); } while (us < B + DBATCH); }
            int need = B - 4;
            if (ss < need) { do { ss = ldv(&scatter_seq); } while (ss < need); }
            float uu[DBATCH], nn[DBATCH], fr[DBATCH];
            #pragma unroll
            for (int i = 0; i < DBATCH; i++) uu[i] = uring[B + i];
            #pragma unroll
            for (int i = 0; i < DBATCH; i++) nn[i] = nnrow[B + 1 + i];
            #pragma unroll
            for (int i = 0; i < DBATCH; i++) {
                int sl = (B + 1 + i) & ACC_M;
                fr[i] = acc[sl];
                acc[sl] = 0.0f;
            }
            #pragma unroll
            for (int i = 0; i < DBATCH; i++) {
                int t = B + i;
                float x0 = __fadd_rn(nn[i], __fadd_rn(fr[i], f2));
                float x1 = __fadd_rn(nn[i], __fadd_rn(fr[i], __fadd_rn(wd0, f2)));
                float Pn0 = sigP(x0);
                float Pn1 = sigP(x1);
                float P   = sp_prev ? Pc1 : Pc0;
                bool  sp  = (uu[i] < P);
                float spf = sp ? 1.0f : 0.0f;
                Sout[t] = spf;
                Pout[t] = P;
                spikering[t] = spf;
                f2  = __fmaf_rn(wd1,  spf, f3);
                f3  = __fmaf_rn(wd2,  spf, f4);
                f4  = __fmaf_rn(wd3,  spf, f5);
                f5  = __fmaf_rn(wd4,  spf, f6);
                f6  = __fmaf_rn(wd5,  spf, f7);
                f7  = __fmaf_rn(wd6,  spf, f8);
                f8  = __fmaf_rn(wd7,  spf, f9);
                f9  = __fmaf_rn(wd8,  spf, f10);
                f10 = __fmaf_rn(wd9,  spf, f11);
                f11 = __fmaf_rn(wd10, spf, f12);
                f12 = __fmul_rn(wd11, spf);
                Pc0 = Pn0; Pc1 = Pn1; sp_prev = sp;
                if (i & 1) st_rel(&dec_seq, t + 1);
            }
        }
    } else if (tid >= 96) {
        // scatter — verbatim
        const int lane = tid - 96;
        int ds = 0;
        for (int base = 0; base < T_STEPS; base += 2) {
            if (ds < base + 2) { do { ds = ldv(&dec_seq); } while (ds < base + 2); }
            #pragma unroll
            for (int q = 0; q < 2; q++) {
                int t = base + q;
                float spf = spikering[t];
                #pragma unroll 4
                for (int d = NEAR + 1 + lane; d <= TNO; d += 32) {
                    int sl = (t + d) & ACC_M;
                    acc[sl] = __fmaf_rn(wdel[d - 1], spf, acc[sl]);
                }
            }
            __syncwarp();
            if (lane == 0) st_rel(&scatter_seq, base + 2);
        }
    }
}

// ===========================================================================
// REAL KERNEL — R7 verbatim (known: 1046.7us, rel_err 8.087631e-8)
// ===========================================================================
__global__ __launch_bounds__(NTH)
void apnn_kernel(const float *__restrict__ V,  const float *__restrict__ D,
                 const float *__restrict__ w1, const float *__restrict__ b1,
                 const float *__restrict__ w2, const float *__restrict__ b2,
                 const float *__restrict__ Wref, float *__restrict__ out) {
    __shared__ float    nnrow[T_STEPS + DBATCH];
    __shared__ uint32_t subring[T_STEPS][2];
    __shared__ float    uring[T_STEPS];
    __shared__ float    spikering[T_STEPS];
    __shared__ float    acc[ACC_N];
    __shared__ float    wdel[TNO];
    __shared__ int      chain_seq, u_seq, dec_seq, scatter_seq;

    const int tid = threadIdx.x;
    const int b   = blockIdx.x;

    if (tid == 0) { chain_seq = 0; u_seq = 0; dec_seq = 0; scatter_seq = 0; }
    __syncthreads();

    if (tid == 0) {
        uint32_t k0 = 0u, k1 = 42u;
        for (int base = 0; base < T_STEPS; base += 2) {
            uint32_t nk0, nk1, s0, s1;
            tf2x32(k0, k1, 0u, 0u, nk0, nk1);
            tf2x32(k0, k1, 0u, 1u, s0, s1);
            subring[base][0] = s0;  subring[base][1] = s1;
            k0 = nk0; k1 = nk1;
            tf2x32(k0, k1, 0u, 0u, nk0, nk1);
            tf2x32(k0, k1, 0u, 1u, s0, s1);
            subring[base + 1][0] = s0;  subring[base + 1][1] = s1;
            k0 = nk0; k1 = nk1;
            st_rel(&chain_seq, base + 2);
        }
    } else if (tid >= 32 && tid < 36) {
        const int lane = tid - 32;
        int cs = 0;
        for (int base = 0; base < T_STEPS; base += 4) {
            if (cs < base + 4) { do { cs = ldv(&chain_seq); } while (cs < base + 4); }
            int t = base + lane;
            uint32_t s0 = subring[t][0];
            uint32_t s1 = subring[t][1];
            uint32_t y0, y1;
            tf2x32(s0, s1, 0u, (uint32_t)b, y0, y1);
            uint32_t bits = y0 ^ y1;
            uring[t] = __uint_as_float((bits >> 9) | 0x3F800000u) - 1.0f;
            __syncwarp(0xFu);
            if (lane == 0) st_rel(&u_seq, base + 4);
        }
    } else if (tid >= 64) {
        const int itid = tid - 64;
        for (int i = itid; i < ACC_N; i += 64) acc[i] = 0.0f;
        if (itid < DBATCH) nnrow[T_STEPS + itid] = 0.0f;
        for (int j = itid; j < TNO; j += 64) {
            double raw = 7.5 * log(((double)j + 1.0) + 1e-7);
            double cr = cos(raw), sr = sin(raw);
            float s = 0.0f;
            #pragma unroll 1
            for (int i = 0; i < NBASIS; i++) {
                double phi = 1.5707963267948966 * (double)i;
                float bas = 0.0f;
                if (!(raw < phi - 3.141592653589793 || raw > phi + 3.141592653589793)) {
                    double cv;
                    switch (i & 3) {
                        case 0:  cv =  cr; break;
                        case 1:  cv =  sr; break;
                        case 2:  cv = -cr; break;
                        default: cv = -sr; break;
                    }
                    bas = (float)(0.5 * cv + 0.5);
                }
                s = __fmaf_rn(bas, Wref[i], s);
            }
            wdel[j] = s;
        }
        {
            float a0 = w1[0], a1 = w1[1], a2 = w1[2], a3 = w1[3], a4 = w1[4];
            float a5 = w1[5], a6 = w1[6], a7 = w1[7], a8 = w1[8], a9 = w1[9];
            float c0 = b1[0], c1 = b1[1], c2 = b1[2], c3 = b1[3], c4 = b1[4];
            float v0 = w2[0], v1 = w2[1], v2 = w2[2], v3 = w2[3], v4 = w2[4];
            float bb = b2[0];
            const float *Vr = V + (size_t)b * T_STEPS;
            const float *Dr = D + (size_t)b * T_STEPS;
            for (int t = itid; t < T_STEPS; t += 64) {
                float vv = Vr[t], dd = Dr[t];
                float h0 = tanh_xla(__fadd_rn(__fadd_rn(__fmul_rn(a0, vv), __fmul_rn(a1, dd)), c0));
                float h1 = tanh_xla(__fadd_rn(__fadd_rn(__fmul_rn(a2, vv), __fmul_rn(a3, dd)), c1));
                float h2 = tanh_xla(__fadd_rn(__fadd_rn(__fmul_rn(a4, vv), __fmul_rn(a5, dd)), c2));
                float h3 = tanh_xla(__fadd_rn(__fadd_rn(__fmul_rn(a6, vv), __fmul_rn(a7, dd)), c3));
                float h4 = tanh_xla(__fadd_rn(__fadd_rn(__fmul_rn(a8, vv), __fmul_rn(a9, dd)), c4));
                float s = __fmul_rn(v0, h0);
                s = __fadd_rn(s, __fmul_rn(v1, h1));
                s = __fadd_rn(s, __fmul_rn(v2, h2));
                s = __fadd_rn(s, __fmul_rn(v3, h3));
                s = __fadd_rn(s, __fmul_rn(v4, h4));
                nnrow[t] = __fadd_rn(s, bb);
            }
        }
        asm volatile("bar.sync 1, 64;" ::: "memory");

        if (tid == 64) {
            float f2 = 0.f, f3 = 0.f, f4 = 0.f, f5 = 0.f, f6 = 0.f, f7 = 0.f,
                  f8 = 0.f, f9 = 0.f, f10 = 0.f, f11 = 0.f, f12 = 0.f;
            const float wd0 = wdel[0],  wd1 = wdel[1],  wd2 = wdel[2],  wd3 = wdel[3];
            const float wd4 = wdel[4],  wd5 = wdel[5],  wd6 = wdel[6],  wd7 = wdel[7];
            const float wd8 = wdel[8],  wd9 = wdel[9],  wd10 = wdel[10], wd11 = wdel[11];
            float *Sout = out + (size_t)b * T_STEPS;
            float *Pout = out + (size_t)B_ROWS * T_STEPS + (size_t)b * T_STEPS;
            int us = 0, ss = 0;
            float far0 = acc[0]; acc[0] = 0.0f;
            float nn0  = nnrow[0];
            float Pc0 = sigP(__fadd_rn(nn0, __fadd_rn(far0, f2)));
            float Pc1 = sigP(__fadd_rn(nn0, __fadd_rn(far0, __fadd_rn(wd0, f2))));
            bool  sp_prev = false;
            for (int B = 0; B < T_STEPS; B += DBATCH) {
                if (us < B + DBATCH) { do { us = ldv(&u_seq); } while (us < B + DBATCH); }
                int need = B - 4;
                if (ss < need) { do { ss = ldv(&scatter_seq); } while (ss < need); }
                float uu[DBATCH], nn[DBATCH], fr[DBATCH];
                #pragma unroll
                for (int i = 0; i < DBATCH; i++) uu[i] = uring[B + i];
                #pragma unroll
                for (int i = 0; i < DBATCH; i++) nn[i] = nnrow[B + 1 + i];
                #pragma unroll
                for (int i = 0; i < DBATCH; i++) {
                    int sl = (B + 1 + i) & ACC_M;
                    fr[i] = acc[sl];
                    acc[sl] = 0.0f;
                }
                #pragma unroll
                for (int i = 0; i < DBATCH; i++) {
                    int t = B + i;
                    float x0 = __fadd_rn(nn[i], __fadd_rn(fr[i], f2));
                    float x1 = __fadd_rn(nn[i], __fadd_rn(fr[i], __fadd_rn(wd0, f2)));
                    float Pn0 = sigP(x0);
                    float Pn1 = sigP(x1);
                    float P   = sp_prev ? Pc1 : Pc0;
                    bool  sp  = (uu[i] < P);
                    float spf = sp ? 1.0f : 0.0f;
                    Sout[t] = spf;
                    Pout[t] = P;
                    spikering[t] = spf;
                    f2  = __fmaf_rn(wd1,  spf, f3);
                    f3  = __fmaf_rn(wd2,  spf, f4);
                    f4  = __fmaf_rn(wd3,  spf, f5);
                    f5  = __fmaf_rn(wd4,  spf, f6);
                    f6  = __fmaf_rn(wd5,  spf, f7);
                    f7  = __fmaf_rn(wd6,  spf, f8);
                    f8  = __fmaf_rn(wd7,  spf, f9);
                    f9  = __fmaf_rn(wd8,  spf, f10);
                    f10 = __fmaf_rn(wd9,  spf, f11);
                    f11 = __fmaf_rn(wd10, spf, f12);
                    f12 = __fmul_rn(wd11, spf);
                    Pc0 = Pn0; Pc1 = Pn1; sp_prev = sp;
                    if (i & 1) st_rel(&dec_seq, t + 1);
                }
            }
        } else if (tid >= 96) {
            const int lane = tid - 96;
            int ds = 0;
            for (int base = 0; base < T_STEPS; base += 2) {
                if (ds < base + 2) { do { ds = ldv(&dec_seq); } while (ds < base + 2); }
                #pragma unroll
                for (int q = 0; q < 2; q++) {
                    int t = base + q;
                    float spf = spikering[t];
                    #pragma unroll 4
                    for (int d = NEAR + 1 + lane; d <= TNO; d += 32) {
                        int sl = (t + d) & ACC_M;
                        acc[sl] = __fmaf_rn(wdel[d - 1], spf, acc[sl]);
                    }
                }
                __syncwarp();
                if (lane == 0) st_rel(&scatter_seq, base + 2);
            }
        }
    }
}

extern "C" void kernel_launch(void* const* d_in, const int* in_sizes, int n_in,
                              void* d_out, int out_size) {
    const float *V    = (const float*)d_in[0];
    const float *D    = (const float*)d_in[1];
    const float *w1   = (const float*)d_in[2];
    const float *b1   = (const float*)d_in[3];
    const float *w2   = (const float*)d_in[4];
    const float *b2   = (const float*)d_in[5];
    const float *Wref = (const float*)d_in[6];
    float *out = (float*)d_out;
    // real kernel (correct output, known 1046.7us)
    apnn_kernel<<<B_ROWS, NTH>>>(V, D, w1, b1, w2, b2, Wref, out);
    // ablation: dur_us = 1046.7 + 4*C(chain) + D(dec+scatter)
    chain4_kernel<<<B_ROWS, 32>>>();
    dec_scatter_kernel<<<B_ROWS, NTH>>>();
}

// round 11
// speedup vs baseline: 2.3417x; 1.8050x over previous
#include <cuda_runtime.h>
#include <cuda_bf16.h>
#include <cstdint>
#include <math.h>

#define T_STEPS 2048
#define B_ROWS  64
#define TNO     501
#define NBASIS  30
#define ACC_N   512     // far-delay accumulator ring (power of 2 > TNO)
#define ACC_M   511
#define NTH     192     // 6 warps: chain / uniform / P-warp / decision / scatter / init
#define PRM     31      // Pring depth 32 (slots), 32 lanes each

// ---------------------------------------------------------------------------
// Threefry-2x32, 20 rounds — bit-exact port of jax/_src/prng.py threefry2x32
// ---------------------------------------------------------------------------
__device__ __forceinline__ void tf2x32(uint32_t k0, uint32_t k1,
                                       uint32_t x0, uint32_t x1,
                                       uint32_t &o0, uint32_t &o1) {
    uint32_t k2 = k0 ^ k1 ^ 0x1BD11BDAu;
#define TFR(r) { x0 += x1; x1 = __funnelshift_l(x1, x1, (r)); x1 ^= x0; }
    x0 += k0; x1 += k1;
    TFR(13) TFR(15) TFR(26) TFR(6)
    x0 += k1; x1 += k2 + 1u;
    TFR(17) TFR(29) TFR(16) TFR(24)
    x0 += k2; x1 += k0 + 2u;
    TFR(13) TFR(15) TFR(26) TFR(6)
    x0 += k0; x1 += k1 + 3u;
    TFR(17) TFR(29) TFR(16) TFR(24)
    x0 += k1; x1 += k2 + 4u;
    TFR(13) TFR(15) TFR(26) TFR(6)
    x0 += k2; x1 += k0 + 5u;
#undef TFR
    o0 = x0; o1 = x1;
}

// XLA EmitTanh (Eigen rational, clamp [-9,9], |x|<4e-4 -> x), UNcontracted.
// This exact form gave rel_err 8e-8 (zero Bernoulli flips). DO NOT TOUCH.
__device__ __forceinline__ float tanh_xla(float x) {
    float ax = fabsf(x);
    float xc = fminf(fmaxf(x, -9.0f), 9.0f);
    float x2 = __fmul_rn(xc, xc);
    float num = -2.76076847742355e-16f;
    num = __fadd_rn(__fmul_rn(x2, num),  2.00018790482477e-13f);
    num = __fadd_rn(__fmul_rn(x2, num), -8.60467152213735e-11f);
    num = __fadd_rn(__fmul_rn(x2, num),  5.12229709037114e-08f);
    num = __fadd_rn(__fmul_rn(x2, num),  1.48572235717979e-05f);
    num = __fadd_rn(__fmul_rn(x2, num),  6.37261928875436e-04f);
    num = __fadd_rn(__fmul_rn(x2, num),  4.89352455891786e-03f);
    num = __fmul_rn(xc, num);
    float den = 1.19825839466702e-06f;
    den = __fadd_rn(__fmul_rn(x2, den),  1.18534705686654e-04f);
    den = __fadd_rn(__fmul_rn(x2, den),  2.26843463243900e-03f);
    den = __fadd_rn(__fmul_rn(x2, den),  4.89352518554385e-03f);
    float r = __fdiv_rn(num, den);
    return (ax < 0.0004f) ? x : r;
}
// P = 0.5*tanh(0.5*x)+0.5  (bit-identical to the passing kernel's sequence)
__device__ __forceinline__ float sigP(float x) {
    return __fadd_rn(__fmul_rn(0.5f, tanh_xla(__fmul_rn(0.5f, x))), 0.5f);
}

__device__ __forceinline__ void st_rel(int *p, int v) {
    uint32_t a = (uint32_t)__cvta_generic_to_shared(p);
    asm volatile("st.release.cta.shared.b32 [%0], %1;" :: "r"(a), "r"(v) : "memory");
}
__device__ __forceinline__ int ldv(volatile int *p) { return *p; }

// ---------------------------------------------------------------------------
// One block per row b.  Roles (warp = tid/32):
//   warp0 lane0   : key-split chain (serial threefry chain — 253 cy/step floor)
//   warp1 lanes0-3: uniform producers (4 steps per poll)
//   warp2 (all 32): P-warp — 32 speculative sigP candidates per step, one per
//                   lane (5-bit mask of spikes t-1..t-5); tail g6..g12 kept by
//                   R7's verbatim fmaf pipeline fed with resolved s(t-6)
//   warp3 lane0   : decision — select / compare / store only (~20 cy/step)
//   warp4 (all 32): scatter — far delays 13..501 into acc ring (R7 verbatim)
//   warp5         : init help
// Warps 2..5 do init (f64 basis, MLP) then bar.sync 1,128; warps 0,1 free-run.
// ---------------------------------------------------------------------------
__global__ __launch_bounds__(NTH)
void apnn_kernel(const float *__restrict__ V,  const float *__restrict__ D,
                 const float *__restrict__ w1, const float *__restrict__ b1,
                 const float *__restrict__ w2, const float *__restrict__ b2,
                 const float *__restrict__ Wref, float *__restrict__ out) {
    // Pring MUST be 8/16B-aligned: the decision thread uses LDS.64 pair loads.
    // (R10 fault: default 4B alignment after wdel -> misaligned address.)
    __shared__ __align__(16) float Pring[32 * 32]; // P candidates: slot(t&31) x lane
    __shared__ float    nnrow[T_STEPS];          // MLP output, this row
    __shared__ uint32_t subring[T_STEPS][2];     // per-step subkeys
    __shared__ float    uring[T_STEPS];          // per-step uniforms
    __shared__ float    spikepad[T_STEPS + 8];   // spike(t) at [8+t]; front pad 0
    __shared__ float    acc[ACC_N];              // pending far refract
    __shared__ float    wdel[TNO];               // weight for delay j+1
    __shared__ int      chain_seq, u_seq, dec_seq, scatter_seq, pring_seq;

    const int tid = threadIdx.x;
    const int wid = tid >> 5;
    const int b   = blockIdx.x;

    if (tid == 0) {
        chain_seq = 0; u_seq = 0; dec_seq = 0; scatter_seq = 0; pring_seq = 0;
    }
    __syncthreads();

    if (tid == 0) {
        // ---- chain: free-running serial split chain (R7 verbatim)
        uint32_t k0 = 0u, k1 = 42u;              // jax.random.key(42) -> (0,42)
        for (int base = 0; base < T_STEPS; base += 2) {
            uint32_t nk0, nk1, s0, s1;
            tf2x32(k0, k1, 0u, 0u, nk0, nk1);
            tf2x32(k0, k1, 0u, 1u, s0, s1);
            subring[base][0] = s0;  subring[base][1] = s1;
            k0 = nk0; k1 = nk1;
            tf2x32(k0, k1, 0u, 0u, nk0, nk1);
            tf2x32(k0, k1, 0u, 1u, s0, s1);
            subring[base + 1][0] = s0;  subring[base + 1][1] = s1;
            k0 = nk0; k1 = nk1;
            st_rel(&chain_seq, base + 2);
        }
    } else if (tid >= 32 && tid < 36) {
        // ---- uniform: 4 lanes, 4 steps per poll (R7 verbatim)
        const int lane = tid - 32;
        int cs = 0;
        for (int base = 0; base < T_STEPS; base += 4) {
            if (cs < base + 4) { do { cs = ldv(&chain_seq); } while (cs < base + 4); }
            int t = base + lane;
            uint32_t s0 = subring[t][0];
            uint32_t s1 = subring[t][1];
            uint32_t y0, y1;
            tf2x32(s0, s1, 0u, (uint32_t)b, y0, y1);
            uint32_t bits = y0 ^ y1;
            uring[t] = __uint_as_float((bits >> 9) | 0x3F800000u) - 1.0f;
            __syncwarp(0xFu);
            if (lane == 0) st_rel(&u_seq, base + 4);
        }
    } else if (tid >= 64) {
        // ---- init on warps 2..5 (128 threads), overlapped with chain/uniform
        const int itid = tid - 64;
        for (int i = itid; i < ACC_N; i += 128) acc[i] = 0.0f;
        if (itid < 8) spikepad[itid] = 0.0f;     // spikes for t < 0
        // refractory delay weights: wdel[j] = sum_i f32(basis_f64[i,j])*Wref[i]
        for (int j = itid; j < TNO; j += 128) {
            double raw = 7.5 * log(((double)j + 1.0) + 1e-7);
            double cr = cos(raw), sr = sin(raw);
            float s = 0.0f;
            #pragma unroll 1
            for (int i = 0; i < NBASIS; i++) {
                double phi = 1.5707963267948966 * (double)i;
                float bas = 0.0f;
                if (!(raw < phi - 3.141592653589793 || raw > phi + 3.141592653589793)) {
                    double cv;
                    switch (i & 3) {
                        case 0:  cv =  cr; break;
                        case 1:  cv =  sr; break;
                        case 2:  cv = -cr; break;
                        default: cv = -sr; break;
                    }
                    bas = (float)(0.5 * cv + 0.5);
                }
                s = __fmaf_rn(bas, Wref[i], s);
            }
            wdel[j] = s;
        }
        // pointwise MLP (R7 verbatim math)
        {
            float a0 = w1[0], a1 = w1[1], a2 = w1[2], a3 = w1[3], a4 = w1[4];
            float a5 = w1[5], a6 = w1[6], a7 = w1[7], a8 = w1[8], a9 = w1[9];
            float c0 = b1[0], c1 = b1[1], c2 = b1[2], c3 = b1[3], c4 = b1[4];
            float v0 = w2[0], v1 = w2[1], v2 = w2[2], v3 = w2[3], v4 = w2[4];
            float bb = b2[0];
            const float *Vr = V + (size_t)b * T_STEPS;
            const float *Dr = D + (size_t)b * T_STEPS;
            for (int t = itid; t < T_STEPS; t += 128) {
                float vv = Vr[t], dd = Dr[t];
                float h0 = tanh_xla(__fadd_rn(__fadd_rn(__fmul_rn(a0, vv), __fmul_rn(a1, dd)), c0));
                float h1 = tanh_xla(__fadd_rn(__fadd_rn(__fmul_rn(a2, vv), __fmul_rn(a3, dd)), c1));
                float h2 = tanh_xla(__fadd_rn(__fadd_rn(__fmul_rn(a4, vv), __fmul_rn(a5, dd)), c2));
                float h3 = tanh_xla(__fadd_rn(__fadd_rn(__fmul_rn(a6, vv), __fmul_rn(a7, dd)), c3));
                float h4 = tanh_xla(__fadd_rn(__fadd_rn(__fmul_rn(a8, vv), __fmul_rn(a9, dd)), c4));
                float s = __fmul_rn(v0, h0);
                s = __fadd_rn(s, __fmul_rn(v1, h1));
                s = __fadd_rn(s, __fmul_rn(v2, h2));
                s = __fadd_rn(s, __fmul_rn(v3, h3));
                s = __fadd_rn(s, __fmul_rn(v4, h4));
                nnrow[t] = __fadd_rn(s, bb);
            }
        }
        asm volatile("bar.sync 1, 128;" ::: "memory");   // warps 2..5

        if (wid == 2) {
            // ---- P-warp: 32 speculative candidates per step.
            // lane bit j <-> spike(t-1-j) with weight wdel[j] (j=0..4).
            // Tail g6..g12 = R7's f6..f12 pipeline fed with resolved s(t-6).
            const int lane = tid - 64;
            const bool b0 = lane & 1, b1 = lane & 2, b2 = lane & 4,
                       b3 = lane & 8, b4 = lane & 16;
            const float wd0 = wdel[0],  wd1 = wdel[1],  wd2 = wdel[2];
            const float wd3 = wdel[3],  wd4 = wdel[4],  wd5 = wdel[5];
            const float wd6 = wdel[6],  wd7 = wdel[7],  wd8 = wdel[8];
            const float wd9 = wdel[9],  wd10 = wdel[10], wd11 = wdel[11];
            float g6 = 0.f, g7 = 0.f, g8 = 0.f, g9 = 0.f,
                  g10 = 0.f, g11 = 0.f, g12 = 0.f;
            int ds = 0, ss = 0;
            for (int B = 0; B < T_STEPS; B += 2) {
                // step t needs s(t-6) resolved (dec_seq >= t-5) and far slot t
                // complete (scatter_seq >= t-12); take worst over {B, B+1}.
                if (ds < B - 4)  { do { ds = ldv(&dec_seq);     } while (ds < B - 4); }
                if (ss < B - 11) { do { ss = ldv(&scatter_seq); } while (ss < B - 11); }
                #pragma unroll
                for (int q = 0; q < 2; q++) {
                    int t = B + q;
                    float s6 = spikepad[t + 2];          // = spike(t-6), pad zeros
                    // R7's f6..f12 update ops, verbatim, with s = s6
                    g6  = __fmaf_rn(wd5,  s6, g7);
                    g7  = __fmaf_rn(wd6,  s6, g8);
                    g8  = __fmaf_rn(wd7,  s6, g9);
                    g9  = __fmaf_rn(wd8,  s6, g10);
                    g10 = __fmaf_rn(wd9,  s6, g11);
                    g11 = __fmaf_rn(wd10, s6, g12);
                    g12 = __fmul_rn(wd11, s6);
                    // near-sum candidate: innermost delay 5 first (R7 nest order)
                    float v = g6;
                    if (b4) v = __fadd_rn(wd4, v);
                    if (b3) v = __fadd_rn(wd3, v);
                    if (b2) v = __fadd_rn(wd2, v);
                    if (b1) v = __fadd_rn(wd1, v);
                    if (b0) v = __fadd_rn(wd0, v);
                    int sl = t & ACC_M;
                    float far = acc[sl];                 // broadcast read
                    float x = __fadd_rn(nnrow[t], __fadd_rn(far, v));
                    float P = sigP(x);                   // SIMD: 32 sigP at once
                    Pring[(t & PRM) * 32 + lane] = P;
                    if (lane == 0) acc[sl] = 0.0f;       // recycle for t+512
                }
                __syncwarp();
                if (lane == 0) st_rel(&pring_seq, B + 2);
            }
        } else if (tid == 96) {
            // ---- decision: select + compare + store only (~20 cy/step)
            float *Sout = out + (size_t)b * T_STEPS;
            float *Pout = out + (size_t)B_ROWS * T_STEPS + (size_t)b * T_STEPS;
            int us = 0, ps = 0;
            int u4 = 0;                 // bits1..4 = s(t-2..t-5) for prefetch
            bool sp_prev = false;       // s(t-1)
            float Pc0 = 0.f, Pc1 = 0.f;
            for (int B = 0; B < T_STEPS; B += 4) {
                if (us < B + 4) { do { us = ldv(&u_seq); } while (us < B + 4); }
                int needp = B + 5; if (needp > T_STEPS) needp = T_STEPS;
                if (ps < needp) { do { ps = ldv(&pring_seq); } while (ps < needp); }
                if (B == 0) { Pc0 = Pring[0]; Pc1 = Pring[1]; }   // mask 0
                float uu0 = uring[B],     uu1 = uring[B + 1];
                float uu2 = uring[B + 2], uu3 = uring[B + 3];
                float uu[4] = {uu0, uu1, uu2, uu3};
                #pragma unroll
                for (int i = 0; i < 4; i++) {
                    int t = B + i;
                    float P   = sp_prev ? Pc1 : Pc0;
                    bool  sp  = (uu[i] < P);
                    float spf = sp ? 1.0f : 0.0f;
                    Sout[t] = spf;
                    Pout[t] = P;
                    spikepad[8 + t] = spf;
                    // mask for step t+1: bits1..4 = s(t-1..t-4)
                    u4 = ((u4 << 1) & 0x1E) | (sp_prev ? 2 : 0);
                    int tn = t + 1; if (tn > T_STEPS - 1) tn = T_STEPS - 1;
                    float2 pc = *(float2*)&Pring[(tn & PRM) * 32 + u4];
                    Pc0 = pc.x; Pc1 = pc.y;
                    sp_prev = sp;
                    if (i & 1) st_rel(&dec_seq, t + 1);
                }
            }
        } else if (wid == 4) {
            // ---- scatter: far delays d = 13..501 (R7 verbatim; spikepad idx)
            const int lane = tid - 128;
            int ds = 0;
            for (int base = 0; base < T_STEPS; base += 2) {
                if (ds < base + 2) { do { ds = ldv(&dec_seq); } while (ds < base + 2); }
                #pragma unroll
                for (int q = 0; q < 2; q++) {
                    int t = base + q;
                    float spf = spikepad[8 + t];
                    #pragma unroll 4
                    for (int d = 13 + lane; d <= TNO; d += 32) {
                        int sl = (t + d) & ACC_M;   // consecutive lanes: conflict-free
                        acc[sl] = __fmaf_rn(wdel[d - 1], spf, acc[sl]);
                    }
                }
                __syncwarp();
                if (lane == 0) st_rel(&scatter_seq, base + 2);
            }
        }
        // warp5 and idle lanes: done after init/bar
    }
}

extern "C" void kernel_launch(void* const* d_in, const int* in_sizes, int n_in,
                              void* d_out, int out_size) {
    const float *V    = (const float*)d_in[0];
    const float *D    = (const float*)d_in[1];
    const float *w1   = (const float*)d_in[2];
    const float *b1   = (const float*)d_in[3];
    const float *w2   = (const float*)d_in[4];
    const float *b2   = (const float*)d_in[5];
    const float *Wref = (const float*)d_in[6];
    float *out = (float*)d_out;
    apnn_kernel<<<B_ROWS, NTH>>>(V, D, w1, b1, w2, b2, Wref, out);
}

// round 12
// speedup vs baseline: 5.0578x; 2.1598x over previous
#include <cuda_runtime.h>
#include <cuda_bf16.h>
#include <cstdint>
#include <math.h>

#define T_STEPS 2048
#define B_ROWS  64
#define TNO     501
#define NBASIS  30
#define ACC_N   512     // far-delay accumulator ring (power of 2 > TNO)
#define ACC_M   511
#define NTH     128     // 4 warps: chain / uniform / decision(spec) / scatter

// ---------------------------------------------------------------------------
// Threefry-2x32, 20 rounds — bit-exact port of jax/_src/prng.py threefry2x32
// ---------------------------------------------------------------------------
__device__ __forceinline__ void tf2x32(uint32_t k0, uint32_t k1,
                                       uint32_t x0, uint32_t x1,
                                       uint32_t &o0, uint32_t &o1) {
    uint32_t k2 = k0 ^ k1 ^ 0x1BD11BDAu;
#define TFR(r) { x0 += x1; x1 = __funnelshift_l(x1, x1, (r)); x1 ^= x0; }
    x0 += k0; x1 += k1;
    TFR(13) TFR(15) TFR(26) TFR(6)
    x0 += k1; x1 += k2 + 1u;
    TFR(17) TFR(29) TFR(16) TFR(24)
    x0 += k2; x1 += k0 + 2u;
    TFR(13) TFR(15) TFR(26) TFR(6)
    x0 += k0; x1 += k1 + 3u;
    TFR(17) TFR(29) TFR(16) TFR(24)
    x0 += k1; x1 += k2 + 4u;
    TFR(13) TFR(15) TFR(26) TFR(6)
    x0 += k2; x1 += k0 + 5u;
#undef TFR
    o0 = x0; o1 = x1;
}

// XLA EmitTanh (Eigen rational, clamp [-9,9], |x|<4e-4 -> x), UNcontracted.
// This exact form gave rel_err 8e-8 (zero Bernoulli flips). DO NOT TOUCH.
__device__ __forceinline__ float tanh_xla(float x) {
    float ax = fabsf(x);
    float xc = fminf(fmaxf(x, -9.0f), 9.0f);
    float x2 = __fmul_rn(xc, xc);
    float num = -2.76076847742355e-16f;
    num = __fadd_rn(__fmul_rn(x2, num),  2.00018790482477e-13f);
    num = __fadd_rn(__fmul_rn(x2, num), -8.60467152213735e-11f);
    num = __fadd_rn(__fmul_rn(x2, num),  5.12229709037114e-08f);
    num = __fadd_rn(__fmul_rn(x2, num),  1.48572235717979e-05f);
    num = __fadd_rn(__fmul_rn(x2, num),  6.37261928875436e-04f);
    num = __fadd_rn(__fmul_rn(x2, num),  4.89352455891786e-03f);
    num = __fmul_rn(xc, num);
    float den = 1.19825839466702e-06f;
    den = __fadd_rn(__fmul_rn(x2, den),  1.18534705686654e-04f);
    den = __fadd_rn(__fmul_rn(x2, den),  2.26843463243900e-03f);
    den = __fadd_rn(__fmul_rn(x2, den),  4.89352518554385e-03f);
    float r = __fdiv_rn(num, den);
    return (ax < 0.0004f) ? x : r;
}
// P = 0.5*tanh(0.5*x)+0.5  (bit-identical to the passing kernel's sequence)
__device__ __forceinline__ float sigP(float x) {
    return __fadd_rn(__fmul_rn(0.5f, tanh_xla(__fmul_rn(0.5f, x))), 0.5f);
}

__device__ __forceinline__ void st_rel(int *p, int v) {
    uint32_t a = (uint32_t)__cvta_generic_to_shared(p);
    asm volatile("st.release.cta.shared.b32 [%0], %1;" :: "r"(a), "r"(v) : "memory");
}
__device__ __forceinline__ int ldv(volatile int *p) { return *p; }

// ---------------------------------------------------------------------------
// One block per row b.  4 warps:
//   warp0 lane0   : key-split chain (serial threefry — 253 cy/step floor)
//   warp1 lanes0-3: uniform producers (4 steps per poll)
//   warp2 (all 32): decision warp — lane L computes candidate P(t | mask=L)
//                   (R11-validated op sequence), and the SAME warp resolves
//                   step t-5 each slot via shfl from the realized-mask lane.
//                   No cross-warp traffic on the recurrence.
//   warp3 (all 32): scatter — far delays 13..501 into acc ring, 1 step/poll
// Warps 2+3 do init (f64 basis, MLP) then bar.sync 1,64; warps 0,1 free-run.
// ---------------------------------------------------------------------------
__global__ __launch_bounds__(NTH)
void apnn_kernel(const float *__restrict__ V,  const float *__restrict__ D,
                 const float *__restrict__ w1, const float *__restrict__ b1,
                 const float *__restrict__ w2, const float *__restrict__ b2,
                 const float *__restrict__ Wref, float *__restrict__ out) {
    __shared__ float    nnrow[T_STEPS];          // MLP output, this row
    __shared__ uint32_t subring[T_STEPS][2];     // per-step subkeys
    __shared__ float    uring[T_STEPS];          // per-step uniforms
    __shared__ float    spikepad[T_STEPS + 8];   // spike(t) at [8+t]; front pad 0
    __shared__ float    acc[ACC_N];              // pending far refract
    __shared__ float    wdel[TNO];               // weight for delay j+1
    __shared__ int      chain_seq, u_seq, dec_seq, scatter_seq;

    const int tid = threadIdx.x;
    const int wid = tid >> 5;
    const int b   = blockIdx.x;

    if (tid == 0) { chain_seq = 0; u_seq = 0; dec_seq = 0; scatter_seq = 0; }
    __syncthreads();

    if (tid == 0) {
        // ---- chain: free-running serial split chain (R7 verbatim)
        uint32_t k0 = 0u, k1 = 42u;              // jax.random.key(42) -> (0,42)
        for (int base = 0; base < T_STEPS; base += 2) {
            uint32_t nk0, nk1, s0, s1;
            tf2x32(k0, k1, 0u, 0u, nk0, nk1);
            tf2x32(k0, k1, 0u, 1u, s0, s1);
            subring[base][0] = s0;  subring[base][1] = s1;
            k0 = nk0; k1 = nk1;
            tf2x32(k0, k1, 0u, 0u, nk0, nk1);
            tf2x32(k0, k1, 0u, 1u, s0, s1);
            subring[base + 1][0] = s0;  subring[base + 1][1] = s1;
            k0 = nk0; k1 = nk1;
            st_rel(&chain_seq, base + 2);
        }
    } else if (tid >= 32 && tid < 36) {
        // ---- uniform: 4 lanes, 4 steps per poll (R7 verbatim)
        const int lane = tid - 32;
        int cs = 0;
        for (int base = 0; base < T_STEPS; base += 4) {
            if (cs < base + 4) { do { cs = ldv(&chain_seq); } while (cs < base + 4); }
            int t = base + lane;
            uint32_t s0 = subring[t][0];
            uint32_t s1 = subring[t][1];
            uint32_t y0, y1;
            tf2x32(s0, s1, 0u, (uint32_t)b, y0, y1);
            uint32_t bits = y0 ^ y1;
            uring[t] = __uint_as_float((bits >> 9) | 0x3F800000u) - 1.0f;
            __syncwarp(0xFu);
            if (lane == 0) st_rel(&u_seq, base + 4);
        }
    } else if (tid >= 64) {
        // ---- init on warps 2+3 (64 threads), overlapped with chain/uniform
        const int itid = tid - 64;
        for (int i = itid; i < ACC_N; i += 64) acc[i] = 0.0f;
        if (itid < 8) spikepad[itid] = 0.0f;     // spikes for t < 0
        // refractory delay weights: wdel[j] = sum_i f32(basis_f64[i,j])*Wref[i]
        for (int j = itid; j < TNO; j += 64) {
            double raw = 7.5 * log(((double)j + 1.0) + 1e-7);
            double cr = cos(raw), sr = sin(raw);
            float s = 0.0f;
            #pragma unroll 1
            for (int i = 0; i < NBASIS; i++) {
                double phi = 1.5707963267948966 * (double)i;
                float bas = 0.0f;
                if (!(raw < phi - 3.141592653589793 || raw > phi + 3.141592653589793)) {
                    double cv;
                    switch (i & 3) {
                        case 0:  cv =  cr; break;
                        case 1:  cv =  sr; break;
                        case 2:  cv = -cr; break;
                        default: cv = -sr; break;
                    }
                    bas = (float)(0.5 * cv + 0.5);
                }
                s = __fmaf_rn(bas, Wref[i], s);
            }
            wdel[j] = s;
        }
        // pointwise MLP (R7 verbatim math)
        {
            float a0 = w1[0], a1 = w1[1], a2 = w1[2], a3 = w1[3], a4 = w1[4];
            float a5 = w1[5], a6 = w1[6], a7 = w1[7], a8 = w1[8], a9 = w1[9];
            float c0 = b1[0], c1 = b1[1], c2 = b1[2], c3 = b1[3], c4 = b1[4];
            float v0 = w2[0], v1 = w2[1], v2 = w2[2], v3 = w2[3], v4 = w2[4];
            float bb = b2[0];
            const float *Vr = V + (size_t)b * T_STEPS;
            const float *Dr = D + (size_t)b * T_STEPS;
            for (int t = itid; t < T_STEPS; t += 64) {
                float vv = Vr[t], dd = Dr[t];
                float h0 = tanh_xla(__fadd_rn(__fadd_rn(__fmul_rn(a0, vv), __fmul_rn(a1, dd)), c0));
                float h1 = tanh_xla(__fadd_rn(__fadd_rn(__fmul_rn(a2, vv), __fmul_rn(a3, dd)), c1));
                float h2 = tanh_xla(__fadd_rn(__fadd_rn(__fmul_rn(a4, vv), __fmul_rn(a5, dd)), c2));
                float h3 = tanh_xla(__fadd_rn(__fadd_rn(__fmul_rn(a6, vv), __fmul_rn(a7, dd)), c3));
                float h4 = tanh_xla(__fadd_rn(__fadd_rn(__fmul_rn(a8, vv), __fmul_rn(a9, dd)), c4));
                float s = __fmul_rn(v0, h0);
                s = __fadd_rn(s, __fmul_rn(v1, h1));
                s = __fadd_rn(s, __fmul_rn(v2, h2));
                s = __fadd_rn(s, __fmul_rn(v3, h3));
                s = __fadd_rn(s, __fmul_rn(v4, h4));
                nnrow[t] = __fadd_rn(s, bb);
            }
        }
        asm volatile("bar.sync 1, 64;" ::: "memory");   // warps 2+3

        if (wid == 2) {
            // ---- decision warp: lane-parallel speculation + in-warp resolve.
            // Candidate(t) [R11-validated bits]: lane bit j <-> s(t-1-j), wd[j];
            // tail g6..g12 = R7 f6..f12 pipeline fed with resolved s(t-6).
            // Resolve lag K=5: slot p resolves t-5 via shfl(Pc[(p+3)&7], mask).
            const int lane = tid & 31;
            const bool c0 = lane & 1, c1 = lane & 2, c2 = lane & 4,
                       c3 = lane & 8, c4 = lane & 16;
            const float wd0 = wdel[0],  wd1 = wdel[1],  wd2 = wdel[2];
            const float wd3 = wdel[3],  wd4 = wdel[4],  wd5 = wdel[5];
            const float wd6 = wdel[6],  wd7 = wdel[7],  wd8 = wdel[8];
            const float wd9 = wdel[9],  wd10 = wdel[10], wd11 = wdel[11];
            float g6 = 0.f, g7 = 0.f, g8 = 0.f, g9 = 0.f,
                  g10 = 0.f, g11 = 0.f, g12 = 0.f;
            float Pc[8];                       // candidate regs (static idx only)
            #pragma unroll
            for (int i = 0; i < 8; i++) Pc[i] = 0.f;
            float sp_prev = 0.f;               // s(t-6) for next slot's g-update
            unsigned m = 0;                    // realized mask bits s(t5-1..t5-5)
            float *Sout = out + (size_t)b * T_STEPS;
            float *Pout = out + (size_t)B_ROWS * T_STEPS + (size_t)b * T_STEPS;
            int us = 0, ss = 0;
            for (int B = 0; B < T_STEPS; B += 8) {
                // polls (block-amortized)
                if (us < B + 3) { do { us = ldv(&u_seq); } while (us < B + 3); }
                if (ss < B - 9) { do { ss = ldv(&scatter_seq); } while (ss < B - 9); }
                // preload u(t5) for t5 = B-5..B+2 and nn for t = B..B+7
                float uu[8], nnv[8];
                #pragma unroll
                for (int q = 0; q < 8; q++) {
                    int i5 = B + q - 5;
                    uu[q] = uring[i5 < 0 ? 0 : i5];
                }
                #pragma unroll
                for (int q = 0; q < 8; q++) nnv[q] = nnrow[B + q];
                #pragma unroll
                for (int p = 0; p < 8; p++) {
                    const int t = B + p;
                    // tail update with s(t-6) (resolved at previous slot)
                    g6  = __fmaf_rn(wd5,  sp_prev, g7);
                    g7  = __fmaf_rn(wd6,  sp_prev, g8);
                    g8  = __fmaf_rn(wd7,  sp_prev, g9);
                    g9  = __fmaf_rn(wd8,  sp_prev, g10);
                    g10 = __fmaf_rn(wd9,  sp_prev, g11);
                    g11 = __fmaf_rn(wd10, sp_prev, g12);
                    g12 = __fmul_rn(wd11, sp_prev);
                    if (p == 4) {   // gate far-acc for slots 4..7 (need ss >= B-5)
                        if (ss < B - 5) { do { ss = ldv(&scatter_seq); } while (ss < B - 5); }
                    }
                    // far accumulator for step t (all writers <= t-13 applied)
                    int sl = t & ACC_M;
                    float far = acc[sl];
                    if (lane == 0) acc[sl] = 0.0f;   // recycle for t+512
                    // candidate (R11-validated rounding sequence)
                    float v = g6;
                    if (c4) v = __fadd_rn(wd4, v);
                    if (c3) v = __fadd_rn(wd3, v);
                    if (c2) v = __fadd_rn(wd2, v);
                    if (c1) v = __fadd_rn(wd1, v);
                    if (c0) v = __fadd_rn(wd0, v);
                    float x = __fadd_rn(nnv[p], __fadd_rn(far, v));
                    float newP = sigP(x);
                    // resolve step t-5 (candidate from 5 slots ago)
                    float P = __shfl_sync(0xFFFFFFFFu, Pc[(p + 3) & 7], (int)m);
                    int t5 = t - 5;
                    if (t5 >= 0) {                    // uniform; false only B=0,p<5
                        bool  sp  = (uu[p] < P);
                        float spf = sp ? 1.0f : 0.0f;
                        if (lane == 0) {
                            Sout[t5] = spf;
                            Pout[t5] = P;
                            spikepad[8 + t5] = spf;
                            st_rel(&dec_seq, t5 + 1);
                        }
                        m = ((m << 1) | (sp ? 1u : 0u)) & 31u;
                        sp_prev = spf;
                    } else {
                        sp_prev = 0.f;
                    }
                    Pc[p] = newP;
                }
            }
            // epilogue: resolve last 5 steps (t5 = T-5..T-1), cands in Pc[3..7]
            if (us < T_STEPS) { do { us = ldv(&u_seq); } while (us < T_STEPS); }
            #pragma unroll
            for (int p2 = 0; p2 < 5; p2++) {
                int t5 = T_STEPS - 5 + p2;
                float P = __shfl_sync(0xFFFFFFFFu, Pc[3 + p2], (int)m);
                bool  sp  = (uring[t5] < P);
                float spf = sp ? 1.0f : 0.0f;
                if (lane == 0) {
                    Sout[t5] = spf;
                    Pout[t5] = P;
                    spikepad[8 + t5] = spf;
                    st_rel(&dec_seq, t5 + 1);
                }
                m = ((m << 1) | (sp ? 1u : 0u)) & 31u;
            }
        } else {
            // ---- scatter warp: far delays d = 13..501, 1 step per poll
            const int lane = tid - 96;
            // per-lane weights: d = 13 + lane + 32*j
            float wreg[16];
            #pragma unroll
            for (int j = 0; j < 16; j++) {
                int d = 13 + lane + 32 * j;
                wreg[j] = (d <= TNO) ? wdel[d - 1] : 0.0f;
            }
            int ds = 0;
            for (int t = 0; t < T_STEPS; t++) {
                if (ds < t + 1) { do { ds = ldv(&dec_seq); } while (ds < t + 1); }
                float spf = spikepad[8 + t];
                if (spf != 0.0f) {               // uniform branch (broadcast spf)
                    #pragma unroll
                    for (int j = 0; j < 16; j++) {
                        int d = 13 + lane + 32 * j;
                        if (d <= TNO) {          // predicated; no slot aliasing
                            int sl = (t + d) & ACC_M;
                            acc[sl] = __fmaf_rn(wreg[j], spf, acc[sl]);
                        }
                    }
                }
                __syncwarp();
                if (lane == 0) st_rel(&scatter_seq, t + 1);
            }
        }
    }
}

extern "C" void kernel_launch(void* const* d_in, const int* in_sizes, int n_in,
                              void* d_out, int out_size) {
    const float *V    = (const float*)d_in[0];
    const float *D    = (const float*)d_in[1];
    const float *w1   = (const float*)d_in[2];
    const float *b1   = (const float*)d_in[3];
    const float *w2   = (const float*)d_in[4];
    const float *b2   = (const float*)d_in[5];
    const float *Wref = (const float*)d_in[6];
    float *out = (float*)d_out;
    apnn_kernel<<<B_ROWS, NTH>>>(V, D, w1, b1, w2, b2, Wref, out);
}